// round 5
// baseline (speedup 1.0000x reference)
#include <cuda_runtime.h>

// Problem constants (fixed by the reference):
//   encoder_outputs : [B, L, D] f32   = d_in[0]
//   durations       : [B, L]    i32   = d_in[1]
//   frames_positions: [B, T, P] f32   = d_in[2]
//   input_lengths   : [B]       i32   = d_in[3]  (UNUSED by reference)
//   output          : [B, T, D+P] f32
#define BB 16
#define LL 512
#define DD 512
#define TT 4096
#define PP 4

#define DV (DD / 4)          // 128 float4 per encoder row
#define ROW_V (DV + 1)       // 129 float4 per output row (516 floats, 2064 B)

// Scratch: frame -> token index map, -1 for invalid (zero) frames.
__device__ int g_idx[BB * TT];

// ---------------------------------------------------------------------------
// Kernel 1: per-batch inclusive cumsum of durations + scatter token index to
// every frame it covers. One block per batch, 512 threads (one per token).
// Token j covers frames [cum[j-1], cum[j]) -> matches searchsorted(side=right)
// including the zero-duration-token case (empty range, skipped).
// ---------------------------------------------------------------------------
__global__ __launch_bounds__(LL) void build_idx_kernel(const int* __restrict__ dur) {
    __shared__ int s[LL];
    const int b = blockIdx.x;
    const int j = threadIdx.x;

    s[j] = dur[b * LL + j];
    __syncthreads();

    // Hillis-Steele inclusive scan over 512 elements (9 steps)
    #pragma unroll
    for (int off = 1; off < LL; off <<= 1) {
        int v = (j >= off) ? s[j - off] : 0;
        __syncthreads();
        s[j] += v;
        __syncthreads();
    }

    // Initialize the whole frame map to invalid
    #pragma unroll
    for (int t = j; t < TT; t += LL)
        g_idx[b * TT + t] = -1;
    __syncthreads();

    int start = (j == 0) ? 0 : s[j - 1];
    int end   = s[j];
    if (end > TT) end = TT;          // safety clamp (total <= 3584 here)
    for (int t = start; t < end; t++)
        g_idx[b * TT + t] = j;
}

// ---------------------------------------------------------------------------
// Kernel 2: expansion + concat. Each 128-lane group owns one output row:
//   out[row][0:512]   = idx >= 0 ? enc[b][idx][:] : 0
//   out[row][512:516] = frames_positions[row][:]
// All accesses are float4; row stride 129 float4 (2064 B, 16B-aligned).
// blockDim = 512 -> 4 rows per block, grid = B*T/4 = 16384 blocks.
// ---------------------------------------------------------------------------
__global__ __launch_bounds__(512) void expand_kernel(
    const float4* __restrict__ enc,   // [B*L, 128] float4
    const float4* __restrict__ fp,    // [B*T] float4
    float4* __restrict__ out)         // [B*T, 129] float4
{
    const int tid  = threadIdx.x;
    const int grp  = tid >> 7;               // 0..3 row within block
    const int lane = tid & 127;              // float4 column within row
    const int row  = (blockIdx.x << 2) + grp;  // 0 .. B*T-1
    const int b    = row >> 12;              // / TT

    const int idx = g_idx[row];              // broadcast within group (L1 hit)

    float4 v;
    if (idx >= 0) {
        v = enc[((size_t)(b * LL + idx)) * DV + lane];
    } else {
        v = make_float4(0.f, 0.f, 0.f, 0.f);
    }

    float4* orow = out + (size_t)row * ROW_V;
    orow[lane] = v;
    if (lane == 0)
        orow[DV] = fp[row];                  // positions tail, always written
}

extern "C" void kernel_launch(void* const* d_in, const int* in_sizes, int n_in,
                              void* d_out, int out_size) {
    const float* enc = (const float*)d_in[0];
    const int*   dur = (const int*)  d_in[1];
    const float* fp  = (const float*)d_in[2];
    // d_in[3] = input_lengths: unused by the reference.
    (void)in_sizes; (void)n_in; (void)out_size;

    build_idx_kernel<<<BB, LL>>>(dur);

    expand_kernel<<<(BB * TT) / 4, 512>>>(
        (const float4*)enc,
        (const float4*)fp,
        (float4*)d_out);
}

// round 6
// speedup vs baseline: 1.5344x; 1.5344x over previous
#include <cuda_runtime.h>

// Problem constants (fixed by the reference):
//   encoder_outputs : [B, L, D] f32   = d_in[0]
//   durations       : [B, L]    i32   = d_in[1]
//   frames_positions: [B, T, P] f32   = d_in[2]
//   input_lengths   : [B]       i32   = d_in[3]  (UNUSED by reference)
//   output          : [B, T, D+P] f32
#define BB 16
#define LL 512
#define DD 512
#define TT 4096
#define PP 4

#define DV (DD / 4)          // 128 float4 per encoder row
#define ROW_V (DV + 1)       // 129 float4 per output row (516 floats, 2064 B)
#define RPG 4                // rows per 128-lane group (ILP batch)

// Scratch: frame -> token index map, -1 for invalid (padding) frames.
__device__ int g_idx[BB * TT];

// ---------------------------------------------------------------------------
// Kernel 1: per-batch inclusive cumsum of durations + scatter token index to
// every frame it covers. One block per batch, 512 threads (one per token).
// Token j covers frames [cum[j-1], cum[j]) -> matches searchsorted(side=right)
// including the zero-duration-token case (empty range, skipped).
// ---------------------------------------------------------------------------
__global__ __launch_bounds__(LL) void build_idx_kernel(const int* __restrict__ dur) {
    __shared__ int s[LL];
    const int b = blockIdx.x;
    const int j = threadIdx.x;

    s[j] = dur[b * LL + j];
    __syncthreads();

    // Hillis-Steele inclusive scan over 512 elements (9 steps)
    #pragma unroll
    for (int off = 1; off < LL; off <<= 1) {
        int v = (j >= off) ? s[j - off] : 0;
        __syncthreads();
        s[j] += v;
        __syncthreads();
    }

    // Initialize the whole frame map to invalid
    #pragma unroll
    for (int t = j; t < TT; t += LL)
        g_idx[b * TT + t] = -1;
    __syncthreads();

    int start = (j == 0) ? 0 : s[j - 1];
    int end   = s[j];
    if (end > TT) end = TT;          // safety clamp (total <= 3584 here)
    for (int t = start; t < end; t++)
        g_idx[b * TT + t] = j;
}

// ---------------------------------------------------------------------------
// Kernel 2: expansion + concat, ILP-batched.
// Each 128-lane group owns RPG=4 CONSECUTIVE output rows:
//   - 4 independent g_idx loads issued back-to-back
//   - 4 independent enc float4 gathers (consecutive rows usually share a
//     token -> L1/L2 hits)
//   - 4 independent float4 stores
//   - lanes 0..3 each store one row's positions tail (no lane-0 serialization)
// blockDim = 512 -> 4 groups -> 16 rows per block, grid = B*T/16 = 4096.
// All 4 rows of a group lie in the same batch (4096 % 16 == 0).
// ---------------------------------------------------------------------------
__global__ __launch_bounds__(512) void expand_kernel(
    const float4* __restrict__ enc,   // [B*L, 128] float4
    const float4* __restrict__ fp,    // [B*T] float4
    float4* __restrict__ out)         // [B*T, 129] float4
{
    const int tid  = threadIdx.x;
    const int grp  = tid >> 7;                     // 0..3 group within block
    const int lane = tid & 127;                    // float4 column within row
    const int row0 = blockIdx.x * (4 * RPG) + grp * RPG;  // first of 4 rows
    const int b    = row0 >> 12;                   // / TT (same for all 4 rows)

    // Phase 1: 4 independent index loads
    int idx[RPG];
    #pragma unroll
    for (int r = 0; r < RPG; r++)
        idx[r] = g_idx[row0 + r];

    // Phase 2: 4 independent encoder gathers (or zero-fill)
    const float4* encb = enc + (size_t)b * LL * DV;
    float4 v[RPG];
    #pragma unroll
    for (int r = 0; r < RPG; r++) {
        if (idx[r] >= 0)
            v[r] = encb[(size_t)idx[r] * DV + lane];
        else
            v[r] = make_float4(0.f, 0.f, 0.f, 0.f);
    }

    // Phase 3: 4 independent stores
    #pragma unroll
    for (int r = 0; r < RPG; r++)
        out[(size_t)(row0 + r) * ROW_V + lane] = v[r];

    // Positions tail: lanes 0..3 handle one row each
    if (lane < RPG)
        out[(size_t)(row0 + lane) * ROW_V + DV] = fp[row0 + lane];
}

extern "C" void kernel_launch(void* const* d_in, const int* in_sizes, int n_in,
                              void* d_out, int out_size) {
    const float* enc = (const float*)d_in[0];
    const int*   dur = (const int*)  d_in[1];
    const float* fp  = (const float*)d_in[2];
    // d_in[3] = input_lengths: unused by the reference.
    (void)in_sizes; (void)n_in; (void)out_size;

    build_idx_kernel<<<BB, LL>>>(dur);

    expand_kernel<<<(BB * TT) / (4 * RPG), 512>>>(
        (const float4*)enc,
        (const float4*)fp,
        (float4*)d_out);
}

// round 7
// speedup vs baseline: 1.7477x; 1.1390x over previous
#include <cuda_runtime.h>

// Problem constants (fixed by the reference):
//   encoder_outputs : [B, L, D] f32   = d_in[0]
//   durations       : [B, L]    i32   = d_in[1]
//   frames_positions: [B, T, P] f32   = d_in[2]
//   input_lengths   : [B]       i32   = d_in[3]  (UNUSED by reference)
//   output          : [B, T, D+P] f32
#define BB 16
#define LL 512
#define DD 512
#define TT 4096
#define PP 4

#define DV (DD / 4)          // 128 float4 per encoder row
#define ROW_V (DV + 1)       // 129 float4 per output row (516 floats, 2064 B)
#define RPG 8                // rows per 128-lane group (ILP batch)

// Scratch: frame -> token index map, -1 for invalid (padding) frames.
__device__ int g_idx[BB * TT];

// ---------------------------------------------------------------------------
// Kernel 1: per-batch inclusive cumsum of durations + scatter token index to
// every frame it covers. One block per batch, 512 threads (one per token).
// Token j covers frames [cum[j-1], cum[j]) -> matches searchsorted(side=right)
// including the zero-duration-token case (empty range, skipped).
// ---------------------------------------------------------------------------
__global__ __launch_bounds__(LL) void build_idx_kernel(const int* __restrict__ dur) {
    __shared__ int s[LL];
    const int b = blockIdx.x;
    const int j = threadIdx.x;

    s[j] = dur[b * LL + j];
    __syncthreads();

    // Hillis-Steele inclusive scan over 512 elements (9 steps)
    #pragma unroll
    for (int off = 1; off < LL; off <<= 1) {
        int v = (j >= off) ? s[j - off] : 0;
        __syncthreads();
        s[j] += v;
        __syncthreads();
    }

    // Initialize the whole frame map to invalid
    #pragma unroll
    for (int t = j; t < TT; t += LL)
        g_idx[b * TT + t] = -1;
    __syncthreads();

    int start = (j == 0) ? 0 : s[j - 1];
    int end   = s[j];
    if (end > TT) end = TT;          // safety clamp (total <= 3584 here)
    for (int t = start; t < end; t++)
        g_idx[b * TT + t] = j;
}

// ---------------------------------------------------------------------------
// Kernel 2: expansion + concat, ILP-batched (MLP = 8 per thread).
// Each 128-lane group owns RPG=8 CONSECUTIVE output rows:
//   - 8 independent g_idx loads issued back-to-back
//   - 8 independent enc float4 gathers (consecutive rows usually share a
//     token -> L1/L2 hits; streaming output stores keep enc resident in L2)
//   - 8 independent streaming float4 stores (__stcs: output is write-once)
//   - lanes 0..7 each store one row's positions tail
// blockDim = 512 -> 4 groups -> 32 rows per block, grid = B*T/32 = 2048.
// All 8 rows of a group lie in the same batch (4096 % 32 == 0).
// ---------------------------------------------------------------------------
__global__ __launch_bounds__(512) void expand_kernel(
    const float4* __restrict__ enc,   // [B*L, 128] float4
    const float4* __restrict__ fp,    // [B*T] float4
    float4* __restrict__ out)         // [B*T, 129] float4
{
    const int tid  = threadIdx.x;
    const int grp  = tid >> 7;                     // 0..3 group within block
    const int lane = tid & 127;                    // float4 column within row
    const int row0 = blockIdx.x * (4 * RPG) + grp * RPG;  // first of 8 rows
    const int b    = row0 >> 12;                   // / TT (same for all 8 rows)

    // Phase 1: 8 independent index loads
    int idx[RPG];
    #pragma unroll
    for (int r = 0; r < RPG; r++)
        idx[r] = __ldg(&g_idx[row0 + r]);

    // Phase 2: 8 independent encoder gathers (or zero-fill)
    const float4* encb = enc + (size_t)b * LL * DV;
    float4 v[RPG];
    #pragma unroll
    for (int r = 0; r < RPG; r++) {
        if (idx[r] >= 0)
            v[r] = encb[(size_t)idx[r] * DV + lane];
        else
            v[r] = make_float4(0.f, 0.f, 0.f, 0.f);
    }

    // Phase 3: 8 independent streaming stores (write-once output, evict-first)
    #pragma unroll
    for (int r = 0; r < RPG; r++)
        __stcs(&out[(size_t)(row0 + r) * ROW_V + lane], v[r]);

    // Positions tail: lanes 0..7 handle one row each
    if (lane < RPG)
        __stcs(&out[(size_t)(row0 + lane) * ROW_V + DV], fp[row0 + lane]);
}

extern "C" void kernel_launch(void* const* d_in, const int* in_sizes, int n_in,
                              void* d_out, int out_size) {
    const float* enc = (const float*)d_in[0];
    const int*   dur = (const int*)  d_in[1];
    const float* fp  = (const float*)d_in[2];
    // d_in[3] = input_lengths: unused by the reference.
    (void)in_sizes; (void)n_in; (void)out_size;

    build_idx_kernel<<<BB, LL>>>(dur);

    expand_kernel<<<(BB * TT) / (4 * RPG), 512>>>(
        (const float4*)enc,
        (const float4*)fp,
        (float4*)d_out);
}

// round 8
// speedup vs baseline: 1.7938x; 1.0264x over previous
#include <cuda_runtime.h>

// Problem constants (fixed by the reference):
//   encoder_outputs : [B, L, D] f32   = d_in[0]
//   durations       : [B, L]    i32   = d_in[1]
//   frames_positions: [B, T, P] f32   = d_in[2]
//   input_lengths   : [B]       i32   = d_in[3]  (UNUSED by reference)
//   output          : [B, T, D+P] f32
#define BB 16
#define LL 512
#define DD 512
#define TT 4096
#define PP 4

#define DV (DD / 4)          // 128 float4 per encoder row
#define ROW_V (DV + 1)       // 129 float4 per output row (516 floats, 2064 B)
#define RPG 8                // rows per 128-lane group (ILP batch)

// Scratch: frame -> token index map, -1 for invalid (padding) frames.
__device__ int g_idx[BB * TT];

// ---------------------------------------------------------------------------
// Kernel 1: per-batch inclusive cumsum of durations + scatter token index to
// every frame it covers. One block per batch, 512 threads (one per token).
// Token j covers frames [cum[j-1], cum[j]) -> matches searchsorted(side=right)
// including the zero-duration-token case (empty range, skipped).
// ---------------------------------------------------------------------------
__global__ __launch_bounds__(LL) void build_idx_kernel(const int* __restrict__ dur) {
    __shared__ int s[LL];
    const int b = blockIdx.x;
    const int j = threadIdx.x;

    s[j] = dur[b * LL + j];
    __syncthreads();

    // Hillis-Steele inclusive scan over 512 elements (9 steps)
    #pragma unroll
    for (int off = 1; off < LL; off <<= 1) {
        int v = (j >= off) ? s[j - off] : 0;
        __syncthreads();
        s[j] += v;
        __syncthreads();
    }

    // Initialize the whole frame map to invalid
    #pragma unroll
    for (int t = j; t < TT; t += LL)
        g_idx[b * TT + t] = -1;
    __syncthreads();

    int start = (j == 0) ? 0 : s[j - 1];
    int end   = s[j];
    if (end > TT) end = TT;          // safety clamp (total <= 3584 here)
    for (int t = start; t < end; t++)
        g_idx[b * TT + t] = j;
}

// ---------------------------------------------------------------------------
// Kernel 2: expansion + concat, ILP-batched with a FORCED 8-deep load batch.
// Each 128-lane group owns RPG=8 CONSECUTIVE output rows. A compiler memory
// fence between the gather phase and the store phase prevents ptxas from
// pipelining load[r]->store[r] pairs (which capped effective MLP at ~4 in the
// previous revision, visible as regs=32). All 8 LDG.128 must be in flight
// before the first STG issues.
// blockDim = 512 -> 4 groups -> 32 rows per block, grid = B*T/32 = 2048.
// ---------------------------------------------------------------------------
__global__ __launch_bounds__(512, 2) void expand_kernel(
    const float4* __restrict__ enc,   // [B*L, 128] float4
    const float4* __restrict__ fp,    // [B*T] float4
    float4* __restrict__ out)         // [B*T, 129] float4
{
    const int tid  = threadIdx.x;
    const int grp  = tid >> 7;                     // 0..3 group within block
    const int lane = tid & 127;                    // float4 column within row
    const int row0 = blockIdx.x * (4 * RPG) + grp * RPG;  // first of 8 rows
    const int b    = row0 >> 12;                   // / TT (same for all 8 rows)

    // Phase 0: 8 independent index loads (issued before everything else)
    int idx[RPG];
    #pragma unroll
    for (int r = 0; r < RPG; r++)
        idx[r] = __ldg(&g_idx[row0 + r]);

    // Positions tail value (independent load, overlaps the gathers)
    float4 tail;
    if (lane < RPG)
        tail = fp[row0 + lane];

    // Phase 1: 8 independent encoder gathers (or zero-fill)
    const float4* encb = enc + (size_t)b * LL * DV;
    float4 v[RPG];
    #pragma unroll
    for (int r = 0; r < RPG; r++) {
        if (idx[r] >= 0)
            v[r] = encb[(size_t)idx[r] * DV + lane];
        else
            v[r] = make_float4(0.f, 0.f, 0.f, 0.f);
    }

    // Compiler fence: no memory op may cross. Forces all 8 LDGs to issue
    // before the first STG -> true MLP=8 per thread. Costs registers (~64),
    // which is the point.
    asm volatile("" ::: "memory");

    // Phase 2: 8 independent streaming stores (write-once output, evict-first)
    #pragma unroll
    for (int r = 0; r < RPG; r++)
        __stcs(&out[(size_t)(row0 + r) * ROW_V + lane], v[r]);

    // Positions tail: lanes 0..7 handle one row each
    if (lane < RPG)
        __stcs(&out[(size_t)(row0 + lane) * ROW_V + DV], tail);
}

extern "C" void kernel_launch(void* const* d_in, const int* in_sizes, int n_in,
                              void* d_out, int out_size) {
    const float* enc = (const float*)d_in[0];
    const int*   dur = (const int*)  d_in[1];
    const float* fp  = (const float*)d_in[2];
    // d_in[3] = input_lengths: unused by the reference.
    (void)in_sizes; (void)n_in; (void)out_size;

    build_idx_kernel<<<BB, LL>>>(dur);

    expand_kernel<<<(BB * TT) / (4 * RPG), 512>>>(
        (const float4*)enc,
        (const float4*)fp,
        (float4*)d_out);
}

// round 9
// speedup vs baseline: 1.9106x; 1.0651x over previous
#include <cuda_runtime.h>

// Problem constants (fixed by the reference):
//   encoder_outputs : [B, L, D] f32   = d_in[0]
//   durations       : [B, L]    i32   = d_in[1]
//   frames_positions: [B, T, P] f32   = d_in[2]
//   input_lengths   : [B]       i32   = d_in[3]  (UNUSED by reference)
//   output          : [B, T, D+P] f32
#define BB 16
#define LL 512
#define DD 512
#define TT 4096
#define PP 4

#define DV (DD / 4)          // 128 float4 per encoder row
#define ROW_V (DV + 1)       // 129 float4 per output row (516 floats, 2064 B)
#define RPG 8                // rows per 128-lane group (ILP batch)
#define ROWS_PB 32           // rows per block (4 groups * RPG)
#define BLKS_PER_B (TT / ROWS_PB)   // 128 blocks per batch

// ---------------------------------------------------------------------------
// Single fused kernel.
// Each block owns 32 consecutive output rows of one batch:
//  1. Recompute the batch's inclusive duration cumsum locally (512 values,
//     warp-shuffle scan -> ~100 cycles, free at issue=16%).
//  2. Scatter token indices covering this block's 32-frame window into smem
//     (exact searchsorted(side="right") semantics; -1 = past-total = zeros).
//  3. Round-7 expansion body: 8-deep ILP gather of encoder rows + streaming
//     float4 stores of the 516-float output rows + positions tail.
// This removes the separate build_idx kernel, its global scratch traffic,
// one launch, and the inter-kernel serialization (~0.9us measured).
// ---------------------------------------------------------------------------
__global__ __launch_bounds__(512) void durian_fused_kernel(
    const int*    __restrict__ dur,   // [B, L]
    const float4* __restrict__ enc,   // [B*L, 128] float4
    const float4* __restrict__ fp,    // [B*T] float4
    float4*       __restrict__ out)   // [B*T, 129] float4
{
    __shared__ int s_wsum[16];
    __shared__ int s_idx[ROWS_PB];

    const int tid   = threadIdx.x;
    const int b     = blockIdx.x >> 7;            // / BLKS_PER_B
    const int blk   = blockIdx.x & (BLKS_PER_B - 1);
    const int t0    = blk * ROWS_PB;              // first frame of this block
    const int row0g = b * TT + t0;                // first global output row

    // ---- Phase A: per-batch inclusive cumsum of durations (L=512) --------
    const int lane = tid & 31;
    const int wid  = tid >> 5;                    // 16 warps
    int x = dur[b * LL + tid];                    // one duration per thread
    #pragma unroll
    for (int o = 1; o < 32; o <<= 1) {
        int y = __shfl_up_sync(0xffffffffu, x, o);
        if (lane >= o) x += y;
    }
    if (lane == 31) s_wsum[wid] = x;
    if (tid < ROWS_PB) s_idx[tid] = -1;           // init window map
    __syncthreads();
    if (wid == 0) {
        int w = (lane < 16) ? s_wsum[lane] : 0;
        #pragma unroll
        for (int o = 1; o < 16; o <<= 1) {
            int y = __shfl_up_sync(0xffffffffu, w, o);
            if (lane >= o) w += y;
        }
        if (lane < 16) s_wsum[lane] = w;          // inclusive warp prefix
    }
    __syncthreads();

    // Token tid covers frames [end - d, end) with end = inclusive cumsum.
    const int prefix = (wid == 0) ? 0 : s_wsum[wid - 1];
    const int end    = prefix + x;
    const int d      = dur[b * LL + tid];         // L2/L1 hit (just loaded)
    const int start  = end - d;

    // Scatter into this block's 32-frame window (disjoint ranges, no races)
    int lo = start > t0 ? start : t0;
    int hi = end < t0 + ROWS_PB ? end : t0 + ROWS_PB;
    for (int t = lo; t < hi; t++)
        s_idx[t - t0] = tid;
    __syncthreads();

    // ---- Phase B: expansion + concat (round-7 body) ----------------------
    const int grp   = tid >> 7;                   // 0..3 group within block
    const int flane = tid & 127;                  // float4 column within row
    const int lrow0 = grp * RPG;                  // local first row of group

    int idx[RPG];
    #pragma unroll
    for (int r = 0; r < RPG; r++)
        idx[r] = s_idx[lrow0 + r];                // LDS broadcast

    const float4* encb = enc + (size_t)b * LL * DV;
    float4 v[RPG];
    #pragma unroll
    for (int r = 0; r < RPG; r++) {
        if (idx[r] >= 0)
            v[r] = encb[(size_t)idx[r] * DV + flane];
        else
            v[r] = make_float4(0.f, 0.f, 0.f, 0.f);
    }

    const int rowg = row0g + lrow0;               // first global row of group
    #pragma unroll
    for (int r = 0; r < RPG; r++)
        __stcs(&out[(size_t)(rowg + r) * ROW_V + flane], v[r]);

    // Positions tail: lanes 0..7 of each group handle one row each
    if (flane < RPG)
        __stcs(&out[(size_t)(rowg + flane) * ROW_V + DV], fp[rowg + flane]);
}

extern "C" void kernel_launch(void* const* d_in, const int* in_sizes, int n_in,
                              void* d_out, int out_size) {
    const float* enc = (const float*)d_in[0];
    const int*   dur = (const int*)  d_in[1];
    const float* fp  = (const float*)d_in[2];
    // d_in[3] = input_lengths: unused by the reference.
    (void)in_sizes; (void)n_in; (void)out_size;

    durian_fused_kernel<<<BB * BLKS_PER_B, 512>>>(
        dur,
        (const float4*)enc,
        (const float4*)fp,
        (float4*)d_out);
}